// round 6
// baseline (speedup 1.0000x reference)
#include <cuda_runtime.h>

#define NN      50000
#define NEMAX   800000
#define D       128

// ---------------- scratch (static device globals; no runtime alloc) ----------
__device__ __align__(16) float g_v1[D];
__device__ __align__(16) float g_v2[D];
__device__ float g_C;
__device__ float g_p1[NN];
__device__ float g_p2[NN];
__device__ int   g_count[NN];
__device__ int   g_off[NN + 1];
__device__ int   g_woff[NN];
__device__ unsigned long long g_spack[NEMAX];      // {src:hi32, attn:lo32}
__device__ __align__(16) float g_agg[(size_t)NN * D];

// ---------------- K0: v1 = W^T a1, v2 = W^T a2, C = b.a1 + b.a2 + a_bias ------
__global__ void k_prep(const float* __restrict__ W, const float* __restrict__ wb,
                       const float* __restrict__ aw, const float* __restrict__ ab) {
    int k = threadIdx.x;   // 0..127
    float v1 = 0.f, v2 = 0.f;
#pragma unroll 4
    for (int j = 0; j < D; j++) {
        float w = W[j * D + k];
        v1 += w * aw[j];
        v2 += w * aw[D + j];
    }
    g_v1[k] = v1;
    g_v2[k] = v2;
    if (k == 0) {
        float c = ab[0];
        for (int j = 0; j < D; j++) c += wb[j] * (aw[j] + aw[D + j]);
        g_C = c;
    }
}

// ---------------- K1: per-node p1, p2; zero counts (warp per node) ------------
__global__ void k_node(const float4* __restrict__ emb4, int n) {
    int w = blockIdx.x * 8 + (threadIdx.x >> 5);
    if (w >= n) return;
    int lane = threadIdx.x & 31;
    float4 e  = emb4[w * 32 + lane];
    float4 a1 = *(const float4*)&g_v1[lane * 4];
    float4 a2 = *(const float4*)&g_v2[lane * 4];
    float d1 = e.x * a1.x + e.y * a1.y + e.z * a1.z + e.w * a1.w;
    float d2 = e.x * a2.x + e.y * a2.y + e.z * a2.z + e.w * a2.w;
#pragma unroll
    for (int o = 16; o; o >>= 1) {
        d1 += __shfl_xor_sync(0xffffffffu, d1, o);
        d2 += __shfl_xor_sync(0xffffffffu, d2, o);
    }
    if (lane == 0) {
        g_p1[w] = d1;
        g_p2[w] = d2;
        g_count[w] = 0;
    }
}

// ---------------- K2: histogram of dst (edges stored as int32) ---------------
__global__ void k_count(const int* __restrict__ edges, int ne, int n) {
    int e = blockIdx.x * blockDim.x + threadIdx.x;
    if (e >= ne) return;
    int dst = edges[e];
    if ((unsigned)dst < (unsigned)n) atomicAdd(&g_count[dst], 1);
}

// ---------------- K3: single-block exclusive scan -> off, woff ---------------
__global__ void k_scan(int n) {
    __shared__ int part[1024];
    int t = threadIdx.x;
    int chunk = (n + 1023) >> 10;
    int start = t * chunk;
    int end   = min(start + chunk, n);
    int s = 0;
    for (int i = start; i < end; i++) s += g_count[i];
    part[t] = s;
    __syncthreads();
    // Hillis-Steele inclusive scan
    for (int dd = 1; dd < 1024; dd <<= 1) {
        int v = (t >= dd) ? part[t - dd] : 0;
        __syncthreads();
        part[t] += v;
        __syncthreads();
    }
    int run = (t == 0) ? 0 : part[t - 1];
    for (int i = start; i < end; i++) {
        g_off[i]  = run;
        g_woff[i] = run;
        run += g_count[i];
    }
    if (t == 1023) g_off[n] = part[1023];
}

// ---------------- K4: attn + scatter edges sorted by dst ---------------------
__global__ void k_scatter(const int* __restrict__ edges, int ne, int n) {
    int e = blockIdx.x * blockDim.x + threadIdx.x;
    if (e >= ne) return;
    int dst = edges[e];
    int src = edges[ne + e];
    if ((unsigned)dst >= (unsigned)n || (unsigned)src >= (unsigned)n) return;
    float sc = g_p1[dst] + g_p2[src] + g_C;
    sc = sc > 0.f ? sc : 0.2f * sc;
    float attn = expf(sc);
    int pos = atomicAdd(&g_woff[dst], 1);
    g_spack[pos] = ((unsigned long long)(unsigned)src << 32) | (unsigned long long)__float_as_uint(attn);
}

// ---------------- K5: segmented aggregation (warp per node) ------------------
__global__ void k_agg(const float4* __restrict__ emb4, int n) {
    int i = blockIdx.x * 8 + (threadIdx.x >> 5);
    if (i >= n) return;
    int lane = threadIdx.x & 31;
    int beg = g_off[i], end = g_off[i + 1];
    float ax = 0.f, ay = 0.f, az = 0.f, aw = 0.f, den = 0.f;
    for (int e = beg; e < end; e++) {
        unsigned long long pk = g_spack[e];
        float a = __uint_as_float((unsigned)pk);
        int   s = (int)(pk >> 32);
        float4 v = emb4[s * 32 + lane];
        ax += a * v.x; ay += a * v.y; az += a * v.z; aw += a * v.w;
        den += a;
    }
    float sc1 = 1.0f / (den + 1e-20f);
    float4 o; o.x = ax * sc1; o.y = ay * sc1; o.z = az * sc1; o.w = aw * sc1;
    ((float4*)g_agg)[i * 32 + lane] = o;
}

// ---------------- K6: fused [emb|agg] @ T^T + bias + LayerNorm ---------------
// Block: 256 threads = 32 lanes (j-groups) x 8 warps (node-groups).
// Thread computes a 4x4 register tile: nodes 4*ig..+3, outputs 4*jg..+3.
// Smem: Tt = transposed T panel, 64 k-rows x 132 (j in 0..127, padded);
//       Xt = transposed X panel, 64 k-rows x 36  (i in 0..31, padded).
// Inner loop: 1 conflict-free LDS.128 (Tt) + 1 broadcast LDS.128 (Xt) + 16 FFMA.
#define TT_STR 132
#define XT_STR 36

__global__ void __launch_bounds__(256) k_epi(
    const float4* __restrict__ emb4,
    const float*  __restrict__ T,
    const float*  __restrict__ tb,
    const float*  __restrict__ gamma,
    const float*  __restrict__ beta,
    float*        __restrict__ out, int n)
{
    __shared__ __align__(16) float Tt[64 * TT_STR];   // 33792 B
    __shared__ __align__(16) float Xt[64 * XT_STR];   //  9216 B

    int tid = threadIdx.x;
    int jg  = tid & 31;        // lane  -> output group (j = 4*jg + r)
    int ig  = tid >> 5;        // warp  -> node group   (i = 4*ig + c)
    int nb  = blockIdx.x * 32;
    const float4* agg4 = (const float4*)g_agg;
    const float4* T4   = (const float4*)T;

    float acc[16];
#pragma unroll
    for (int q = 0; q < 16; q++) acc[q] = 0.f;

    for (int p = 0; p < 4; p++) {
        __syncthreads();   // prior panel fully consumed
        // T panel: rows j = 0..127, k-slice [p*64, p*64+64), stored transposed
        for (int it = tid; it < 2048; it += 256) {
            int j = it >> 4, k4 = it & 15;
            float4 v = T4[j * 64 + p * 16 + k4];
            int kr = k4 * 4;
            Tt[(kr + 0) * TT_STR + j] = v.x;
            Tt[(kr + 1) * TT_STR + j] = v.y;
            Tt[(kr + 2) * TT_STR + j] = v.z;
            Tt[(kr + 3) * TT_STR + j] = v.w;
        }
        // X panel: 32 nodes, k-slice [p*64, p*64+64), [emb|agg] concatenated
        for (int it = tid; it < 512; it += 256) {
            int i = it >> 4, k4 = it & 15;
            int node = nb + i;
            int k = p * 64 + k4 * 4;
            float4 v = make_float4(0.f, 0.f, 0.f, 0.f);
            if (node < n)
                v = (k < 128) ? emb4[node * 32 + (k >> 2)]
                              : agg4[node * 32 + ((k - 128) >> 2)];
            int kr = k4 * 4;
            Xt[(kr + 0) * XT_STR + i] = v.x;
            Xt[(kr + 1) * XT_STR + i] = v.y;
            Xt[(kr + 2) * XT_STR + i] = v.z;
            Xt[(kr + 3) * XT_STR + i] = v.w;
        }
        __syncthreads();

        const float4* Tt4 = (const float4*)Tt;   // row stride 33 float4
        const float4* Xt4 = (const float4*)Xt;   // row stride  9 float4
#pragma unroll 4
        for (int k = 0; k < 64; k++) {
            float4 t = Tt4[k * 33 + jg];   // t.{x,y,z,w} = T[4jg+0..3][k]
            float4 x = Xt4[k * 9 + ig];    // x.{x,y,z,w} = X[4ig+0..3][k]
            acc[ 0] += t.x * x.x; acc[ 1] += t.y * x.x; acc[ 2] += t.z * x.x; acc[ 3] += t.w * x.x;
            acc[ 4] += t.x * x.y; acc[ 5] += t.y * x.y; acc[ 6] += t.z * x.y; acc[ 7] += t.w * x.y;
            acc[ 8] += t.x * x.z; acc[ 9] += t.y * x.z; acc[10] += t.z * x.z; acc[11] += t.w * x.z;
            acc[12] += t.x * x.w; acc[13] += t.y * x.w; acc[14] += t.z * x.w; acc[15] += t.w * x.w;
        }
    }

    __syncthreads();           // Tt reads done; reuse as h staging
    float* hs = Tt;            // 32 rows x TT_STR
    float b0 = tb[4 * jg + 0], b1 = tb[4 * jg + 1], b2 = tb[4 * jg + 2], b3 = tb[4 * jg + 3];
#pragma unroll
    for (int c = 0; c < 4; c++) {
        int i = 4 * ig + c;
        hs[i * TT_STR + 4 * jg + 0] = acc[c * 4 + 0] + b0;
        hs[i * TT_STR + 4 * jg + 1] = acc[c * 4 + 1] + b1;
        hs[i * TT_STR + 4 * jg + 2] = acc[c * 4 + 2] + b2;
        hs[i * TT_STR + 4 * jg + 3] = acc[c * 4 + 3] + b3;
    }
    __syncthreads();

    // LayerNorm: warp ig handles nodes 4*ig..4*ig+3
    int lane = jg;
#pragma unroll
    for (int q = 0; q < 4; q++) {
        int i = ig * 4 + q;
        int node = nb + i;
        float4 v = *(const float4*)&hs[i * TT_STR + lane * 4];
        float s  = v.x + v.y + v.z + v.w;
        float ss = v.x * v.x + v.y * v.y + v.z * v.z + v.w * v.w;
#pragma unroll
        for (int o = 16; o; o >>= 1) {
            s  += __shfl_xor_sync(0xffffffffu, s,  o);
            ss += __shfl_xor_sync(0xffffffffu, ss, o);
        }
        float mu  = s * (1.0f / 128.0f);
        float var = ss * (1.0f / 128.0f) - mu * mu;
        float rs  = rsqrtf(var + 1e-5f);
        if (node < n) {
            float4 g  = *(const float4*)&gamma[lane * 4];
            float4 bb = *(const float4*)&beta[lane * 4];
            float4 o4;
            o4.x = (v.x - mu) * rs * g.x + bb.x;
            o4.y = (v.y - mu) * rs * g.y + bb.y;
            o4.z = (v.z - mu) * rs * g.z + bb.z;
            o4.w = (v.w - mu) * rs * g.w + bb.w;
            *(float4*)&out[node * 128 + lane * 4] = o4;
        }
    }
}

// ---------------- launch -----------------------------------------------------
extern "C" void kernel_launch(void* const* d_in, const int* in_sizes, int n_in,
                              void* d_out, int out_size) {
    const float* emb   = (const float*)d_in[0];
    const int*   edges = (const int*)d_in[1];       // int64 downcast to int32 by harness
    const float* W     = (const float*)d_in[2];
    const float* wb    = (const float*)d_in[3];
    const float* aw    = (const float*)d_in[4];
    const float* ab    = (const float*)d_in[5];
    const float* T     = (const float*)d_in[6];
    const float* tbias = (const float*)d_in[7];
    const float* gam   = (const float*)d_in[8];
    const float* bet   = (const float*)d_in[9];
    float* out = (float*)d_out;

    int n  = in_sizes[0] / D;   // nodes
    int ne = in_sizes[1] / 2;   // edges

    k_prep   <<<1, 128>>>(W, wb, aw, ab);
    k_node   <<<(n + 7) / 8, 256>>>((const float4*)emb, n);
    k_count  <<<(ne + 255) / 256, 256>>>(edges, ne, n);
    k_scan   <<<1, 1024>>>(n);
    k_scatter<<<(ne + 255) / 256, 256>>>(edges, ne, n);
    k_agg    <<<(n + 7) / 8, 256>>>((const float4*)emb, n);
    k_epi    <<<(n + 31) / 32, 256>>>((const float4*)emb, T, tbias, gam, bet, out, n);
}